// round 11
// baseline (speedup 1.0000x reference)
#include <cuda_runtime.h>
#include <cuda_bf16.h>

// Problem constants (fixed by the dataset)
#define MAXN 100000
#define MAXE 3200000
#define INC1 64
#define HIDC 128
#define OUTC2 64
#define CAP 128              // per-node bucket capacity; in-deg ~ Poisson(32), P(>128) ~ 1e-40

// ---------------- device scratch (no allocations allowed) ----------------
__device__ float g_buf_o1[MAXN * HIDC];  // relu(layer1 output)            [N,128]
__device__ float g_buf_xs[MAXN * INC1];  // dinv*x, later reused for g2     [N,64]
__device__ float g_buf_a [MAXN * INC1];  // aggregated xs                   [N,64]
__device__ int   g_cursor[MAXN];         // absolute write cursor per bucket
__device__ int   g_col[MAXN * CAP];      // bucketed adjacency (src ids)
__device__ float g_dinv[MAXN];

// ---------------- bucket build ----------------
__global__ void init_cursor_kernel(int n) {
    int i = blockIdx.x * blockDim.x + threadIdx.x;
    if (i < n) g_cursor[i] = i * CAP;
}

// 4 edges per thread via int4 loads; atomic cursor allocates bucket slots.
__global__ void fill_kernel(const int* __restrict__ src,
                            const int* __restrict__ dst, int E) {
    int i = blockIdx.x * blockDim.x + threadIdx.x;
    int e = i << 2;
    if (e + 3 < E) {
        int4 s4 = *reinterpret_cast<const int4*>(src + e);
        int4 d4 = *reinterpret_cast<const int4*>(dst + e);
        g_col[atomicAdd(&g_cursor[d4.x], 1)] = s4.x;
        g_col[atomicAdd(&g_cursor[d4.y], 1)] = s4.y;
        g_col[atomicAdd(&g_cursor[d4.z], 1)] = s4.z;
        g_col[atomicAdd(&g_cursor[d4.w], 1)] = s4.w;
    } else if (e < E) {
        for (int k = e; k < E; k++)
            g_col[atomicAdd(&g_cursor[dst[k]], 1)] = src[k];
    }
}

// ---------------- xs = dinv .* x  (also materializes dinv from cursor) ----------------
__global__ void scale_x_kernel(const float* __restrict__ X, float* __restrict__ XS, int n) {
    int i = blockIdx.x * blockDim.x + threadIdx.x;      // one float4 per thread
    if (i >= n * 16) return;
    int row = i >> 4;
    int cnt = g_cursor[row] - row * CAP;                // in-degree (no self loop)
    float di = rsqrtf((float)(cnt + 1));
    if ((i & 15) == 0) g_dinv[row] = di;
    float4 v = ((const float4*)X)[i];
    v.x *= di; v.y *= di; v.z *= di; v.w *= di;
    ((float4*)XS)[i] = v;
}

// ---------------- Aggregation (bucket gather), one warp per node, 64 ch ----------------
// Row = 16 x float4. Half-warps process two edges in parallel:
// lanes 0-15 -> even edge, lanes 16-31 -> odd edge; combined at the end with
// 4 shfl_xor(16). Per 4-edge batch: 2 LDG.128 + 1 index LDG per lane (was 4 LDG.64
// + 4 index LDG per lane in the float2 version) -- same sectors, half the issue slots.
// acc init = G[d] on half 0 (self loop). EPI=1: dinv*acc + b, else raw sum.
template <int EPI>
__global__ void __launch_bounds__(256)
agg64_kernel(const float* __restrict__ G, const float* __restrict__ b,
             float* __restrict__ O, int n) {
    int warp = (blockIdx.x * blockDim.x + threadIdx.x) >> 5;
    int lane = threadIdx.x & 31;
    if (warp >= n) return;
    const int d = warp;
    const int half = lane >> 4;          // 0: even edges, 1: odd edges
    const int hl   = lane & 15;          // float4 slot within row
    const float4* __restrict__ Gv = (const float4*)G;

    float4 acc = make_float4(0.f, 0.f, 0.f, 0.f);
    if (half == 0) acc = Gv[d * 16 + hl];            // self loop
    int e = d * CAP;
    const int end = g_cursor[d];

    int i0, i1;
    bool have = (e + 4 <= end);
    if (have) { i0 = g_col[e + half]; i1 = g_col[e + 2 + half]; }
    while (have) {
        int c0 = i0, c1 = i1;
        e += 4;
        have = (e + 4 <= end);
        if (have) { i0 = g_col[e + half]; i1 = g_col[e + 2 + half]; }
        float4 a0 = Gv[c0 * 16 + hl];
        float4 a1 = Gv[c1 * 16 + hl];
        acc.x += a0.x; acc.y += a0.y; acc.z += a0.z; acc.w += a0.w;
        acc.x += a1.x; acc.y += a1.y; acc.z += a1.z; acc.w += a1.w;
    }
    // tail: 0..3 edges, two at a time across the half-warps
    for (; e < end; e += 2) {
        if (e + half < end) {
            int s = g_col[e + half];
            float4 a = Gv[s * 16 + hl];
            acc.x += a.x; acc.y += a.y; acc.z += a.z; acc.w += a.w;
        }
    }
    // combine the two half-warp accumulators
    acc.x += __shfl_xor_sync(0xffffffffu, acc.x, 16);
    acc.y += __shfl_xor_sync(0xffffffffu, acc.y, 16);
    acc.z += __shfl_xor_sync(0xffffffffu, acc.z, 16);
    acc.w += __shfl_xor_sync(0xffffffffu, acc.w, 16);

    if (half == 0) {
        if (EPI) {
            const float di = g_dinv[d];
            float4 bi = ((const float4*)b)[hl];
            acc.x = di * acc.x + bi.x;
            acc.y = di * acc.y + bi.y;
            acc.z = di * acc.z + bi.z;
            acc.w = di * acc.w + bi.w;
        }
        ((float4*)O)[d * 16 + hl] = acc;
    }
}

// ---------------- GEMM: G[i,:] = epi( X[i,:] @ W ), RR rows per thread ----------------
// EPI=1: relu(dinv*acc + b) ; EPI=0: dinv*acc   (R5-measured configuration)
template <int INC, int OUTC, int TY, int RR, int RPB, int EPI>
__global__ void __launch_bounds__(OUTC * TY)
gemm_kernel(const float* __restrict__ X, const float* __restrict__ W,
            const float* __restrict__ b, float* __restrict__ G, int n) {
    __shared__ float Ws[INC * OUTC];
    __shared__ float Xs[TY * RR][INC];
    const int tx = threadIdx.x;        // output channel
    const int ty = threadIdx.y;
    const int tid = ty * OUTC + tx;
    const int nthr = OUTC * TY;
    for (int i = tid; i < INC * OUTC; i += nthr) Ws[i] = W[i];
    __syncthreads();
    const int ROWS = TY * RR;
    const int base = blockIdx.x * RPB;
    for (int r0 = 0; r0 < RPB; r0 += ROWS) {
        for (int i = tid; i < ROWS * (INC / 4); i += nthr) {
            int rloc = i / (INC / 4);
            int cc = (i % (INC / 4));
            int rr = base + r0 + rloc;
            float4 v = (rr < n) ? ((const float4*)(X + rr * INC))[cc]
                                : make_float4(0.f, 0.f, 0.f, 0.f);
            *(float4*)&Xs[rloc][cc * 4] = v;
        }
        __syncthreads();
        float acc[RR];
#pragma unroll
        for (int r = 0; r < RR; r++) acc[r] = 0.f;
#pragma unroll 8
        for (int k = 0; k < INC; k++) {
            float w = Ws[k * OUTC + tx];
#pragma unroll
            for (int r = 0; r < RR; r++)
                acc[r] += Xs[ty * RR + r][k] * w;
        }
#pragma unroll
        for (int r = 0; r < RR; r++) {
            int row = base + r0 + ty * RR + r;
            if (row < n) {
                float di = g_dinv[row];
                float v = EPI ? fmaxf(di * acc[r] + b[tx], 0.f) : di * acc[r];
                G[row * OUTC + tx] = v;
            }
        }
        __syncthreads();
    }
}

// ---------------- launch ----------------
extern "C" void kernel_launch(void* const* d_in, const int* in_sizes, int n_in,
                              void* d_out, int out_size) {
    const float* x  = (const float*)d_in[0];
    const int*   ei = (const int*)d_in[1];     // int32 (JAX x64-disabled truncates int64)
    const float* W1 = (const float*)d_in[2];
    const float* b1 = (const float*)d_in[3];
    const float* W2 = (const float*)d_in[4];
    const float* b2 = (const float*)d_in[5];
    float* out = (float*)d_out;

    const int n = in_sizes[0] / INC1;     // 100000
    const int E = in_sizes[1] / 2;        // 3200000
    const int* src = ei;
    const int* dst = ei + E;
    const int e4 = (E + 3) / 4;

    float* d_o1 = nullptr; cudaGetSymbolAddress((void**)&d_o1, g_buf_o1);
    float* d_xs = nullptr; cudaGetSymbolAddress((void**)&d_xs, g_buf_xs);
    float* d_a  = nullptr; cudaGetSymbolAddress((void**)&d_a,  g_buf_a);

    // 1) bucketed adjacency build (no count pass, no scan)
    init_cursor_kernel<<<(n + 255) / 256, 256>>>(n);
    fill_kernel<<<(e4 + 255) / 256, 256>>>(src, dst, E);

    // 2) xs = dinv .* x   (also derives dinv from cursors)
    scale_x_kernel<<<(n * 16 + 255) / 256, 256>>>(x, d_xs, n);
    // 3) a[d] = xs[d] + sum_{s in N(d)} xs[s]    (64-ch gather)
    agg64_kernel<0><<<(n * 32 + 255) / 256, 256>>>(d_xs, nullptr, d_a, n);
    // 4) o1 = relu(dinv .* (a @ W1) + b1)        (64 -> 128)
    gemm_kernel<INC1, HIDC, 2, 4, 64, 1><<<(n + 63) / 64, dim3(HIDC, 2)>>>(d_a, W1, b1, d_o1, n);
    // 5) g2 = dinv .* (o1 @ W2)                  (128 -> 64), reuse xs buffer
    gemm_kernel<HIDC, OUTC2, 4, 4, 64, 0><<<(n + 63) / 64, dim3(OUTC2, 4)>>>(d_o1, W2, nullptr, d_xs, n);
    // 6) out[d] = dinv[d] * (g2[d] + sum g2[s]) + b2   (64-ch gather)
    agg64_kernel<1><<<(n * 32 + 255) / 256, 256>>>(d_xs, b2, out, n);
}

// round 12
// speedup vs baseline: 1.0259x; 1.0259x over previous
#include <cuda_runtime.h>
#include <cuda_bf16.h>

// Problem constants (fixed by the dataset)
#define MAXN 100000
#define MAXE 3200000
#define INC1 64
#define HIDC 128
#define OUTC2 64
#define CAP 128              // per-node bucket capacity; in-deg ~ Poisson(32), P(>128) ~ 1e-40

// ---------------- device scratch (no allocations allowed) ----------------
__device__ float g_buf_o1[MAXN * HIDC];  // relu(layer1 output)            [N,128]
__device__ float g_buf_xs[MAXN * INC1];  // dinv*x, later reused for g2     [N,64]
__device__ float g_buf_a [MAXN * INC1];  // aggregated xs                   [N,64]
__device__ int   g_cursor[MAXN];         // absolute write cursor per bucket
__device__ int   g_col[MAXN * CAP];      // bucketed adjacency (src ids)
__device__ float g_dinv[MAXN];

// ---------------- bucket build ----------------
__global__ void init_cursor_kernel(int n) {
    int i = blockIdx.x * blockDim.x + threadIdx.x;
    if (i < n) g_cursor[i] = i * CAP;
}

// 4 edges per thread via int4 loads; atomic cursor allocates bucket slots.
__global__ void fill_kernel(const int* __restrict__ src,
                            const int* __restrict__ dst, int E) {
    int i = blockIdx.x * blockDim.x + threadIdx.x;
    int e = i << 2;
    if (e + 3 < E) {
        int4 s4 = *reinterpret_cast<const int4*>(src + e);
        int4 d4 = *reinterpret_cast<const int4*>(dst + e);
        g_col[atomicAdd(&g_cursor[d4.x], 1)] = s4.x;
        g_col[atomicAdd(&g_cursor[d4.y], 1)] = s4.y;
        g_col[atomicAdd(&g_cursor[d4.z], 1)] = s4.z;
        g_col[atomicAdd(&g_cursor[d4.w], 1)] = s4.w;
    } else if (e < E) {
        for (int k = e; k < E; k++)
            g_col[atomicAdd(&g_cursor[dst[k]], 1)] = src[k];
    }
}

// ---------------- xs = dinv .* x  (also materializes dinv from cursor) ----------------
__global__ void scale_x_kernel(const float* __restrict__ X, float* __restrict__ XS, int n) {
    int i = blockIdx.x * blockDim.x + threadIdx.x;      // one float4 per thread
    if (i >= n * 16) return;
    int row = i >> 4;
    int cnt = g_cursor[row] - row * CAP;                // in-degree (no self loop)
    float di = rsqrtf((float)(cnt + 1));
    if ((i & 15) == 0) g_dinv[row] = di;
    float4 v = ((const float4*)X)[i];
    v.x *= di; v.y *= di; v.z *= di; v.w *= di;
    ((float4*)XS)[i] = v;
}

// ---------------- Aggregation (bucket gather), one warp per node, 64 ch ----------------
// R10 float2 gather (measured best) + int4 index fetch: bucket base d*CAP is
// 16B-aligned and e steps by 4, so one LDG.128 fetches the whole batch's indices
// (was 4 scalar LDGs). acc init = G[d] (self loop). EPI=1: dinv*acc + b.
template <int EPI>
__global__ void __launch_bounds__(256)
agg64_kernel(const float* __restrict__ G, const float* __restrict__ b,
             float* __restrict__ O, int n) {
    int warp = (blockIdx.x * blockDim.x + threadIdx.x) >> 5;
    int lane = threadIdx.x & 31;
    if (warp >= n) return;
    const int d = warp;
    const float2* __restrict__ Gv = (const float2*)G;
    float2 acc = Gv[d * 32 + lane];              // self loop
    int e = d * CAP;
    const int end = g_cursor[d];
    int4 s;
    bool have = (e + 4 <= end);
    if (have) s = *reinterpret_cast<const int4*>(g_col + e);
    while (have) {
        int4 c = s;
        e += 4;
        have = (e + 4 <= end);
        if (have) s = *reinterpret_cast<const int4*>(g_col + e);
        float2 a0 = Gv[c.x * 32 + lane];
        float2 a1 = Gv[c.y * 32 + lane];
        float2 a2 = Gv[c.z * 32 + lane];
        float2 a3 = Gv[c.w * 32 + lane];
        acc.x += a0.x; acc.y += a0.y;
        acc.x += a1.x; acc.y += a1.y;
        acc.x += a2.x; acc.y += a2.y;
        acc.x += a3.x; acc.y += a3.y;
    }
    for (; e < end; e++) {
        int si = g_col[e];
        float2 a = Gv[si * 32 + lane];
        acc.x += a.x; acc.y += a.y;
    }
    if (EPI) {
        const float di = g_dinv[d];
        float2 bi = ((const float2*)b)[lane];
        acc.x = di * acc.x + bi.x;
        acc.y = di * acc.y + bi.y;
    }
    ((float2*)O)[d * 32 + lane] = acc;
}

// ---------------- GEMM: G[i,:] = epi( X[i,:] @ W ), RR rows per thread ----------------
// EPI=1: relu(dinv*acc + b) ; EPI=0: dinv*acc   (R5/R10-measured configuration)
template <int INC, int OUTC, int TY, int RR, int RPB, int EPI>
__global__ void __launch_bounds__(OUTC * TY)
gemm_kernel(const float* __restrict__ X, const float* __restrict__ W,
            const float* __restrict__ b, float* __restrict__ G, int n) {
    __shared__ float Ws[INC * OUTC];
    __shared__ float Xs[TY * RR][INC];
    const int tx = threadIdx.x;        // output channel
    const int ty = threadIdx.y;
    const int tid = ty * OUTC + tx;
    const int nthr = OUTC * TY;
    for (int i = tid; i < INC * OUTC; i += nthr) Ws[i] = W[i];
    __syncthreads();
    const int ROWS = TY * RR;
    const int base = blockIdx.x * RPB;
    for (int r0 = 0; r0 < RPB; r0 += ROWS) {
        for (int i = tid; i < ROWS * (INC / 4); i += nthr) {
            int rloc = i / (INC / 4);
            int cc = (i % (INC / 4));
            int rr = base + r0 + rloc;
            float4 v = (rr < n) ? ((const float4*)(X + rr * INC))[cc]
                                : make_float4(0.f, 0.f, 0.f, 0.f);
            *(float4*)&Xs[rloc][cc * 4] = v;
        }
        __syncthreads();
        float acc[RR];
#pragma unroll
        for (int r = 0; r < RR; r++) acc[r] = 0.f;
#pragma unroll 8
        for (int k = 0; k < INC; k++) {
            float w = Ws[k * OUTC + tx];
#pragma unroll
            for (int r = 0; r < RR; r++)
                acc[r] += Xs[ty * RR + r][k] * w;
        }
#pragma unroll
        for (int r = 0; r < RR; r++) {
            int row = base + r0 + ty * RR + r;
            if (row < n) {
                float di = g_dinv[row];
                float v = EPI ? fmaxf(di * acc[r] + b[tx], 0.f) : di * acc[r];
                G[row * OUTC + tx] = v;
            }
        }
        __syncthreads();
    }
}

// ---------------- launch ----------------
extern "C" void kernel_launch(void* const* d_in, const int* in_sizes, int n_in,
                              void* d_out, int out_size) {
    const float* x  = (const float*)d_in[0];
    const int*   ei = (const int*)d_in[1];     // int32 (JAX x64-disabled truncates int64)
    const float* W1 = (const float*)d_in[2];
    const float* b1 = (const float*)d_in[3];
    const float* W2 = (const float*)d_in[4];
    const float* b2 = (const float*)d_in[5];
    float* out = (float*)d_out;

    const int n = in_sizes[0] / INC1;     // 100000
    const int E = in_sizes[1] / 2;        // 3200000
    const int* src = ei;
    const int* dst = ei + E;
    const int e4 = (E + 3) / 4;

    float* d_o1 = nullptr; cudaGetSymbolAddress((void**)&d_o1, g_buf_o1);
    float* d_xs = nullptr; cudaGetSymbolAddress((void**)&d_xs, g_buf_xs);
    float* d_a  = nullptr; cudaGetSymbolAddress((void**)&d_a,  g_buf_a);

    // 1) bucketed adjacency build (no count pass, no scan)
    init_cursor_kernel<<<(n + 255) / 256, 256>>>(n);
    fill_kernel<<<(e4 + 255) / 256, 256>>>(src, dst, E);

    // 2) xs = dinv .* x   (also derives dinv from cursors)
    scale_x_kernel<<<(n * 16 + 255) / 256, 256>>>(x, d_xs, n);
    // 3) a[d] = xs[d] + sum_{s in N(d)} xs[s]    (64-ch gather)
    agg64_kernel<0><<<(n * 32 + 255) / 256, 256>>>(d_xs, nullptr, d_a, n);
    // 4) o1 = relu(dinv .* (a @ W1) + b1)        (64 -> 128)
    gemm_kernel<INC1, HIDC, 2, 4, 64, 1><<<(n + 63) / 64, dim3(HIDC, 2)>>>(d_a, W1, b1, d_o1, n);
    // 5) g2 = dinv .* (o1 @ W2)                  (128 -> 64), reuse xs buffer
    gemm_kernel<HIDC, OUTC2, 4, 4, 64, 0><<<(n + 63) / 64, dim3(OUTC2, 4)>>>(d_o1, W2, nullptr, d_xs, n);
    // 6) out[d] = dinv[d] * (g2[d] + sum g2[s]) + b2   (64-ch gather)
    agg64_kernel<1><<<(n * 32 + 255) / 256, 256>>>(d_xs, b2, out, n);
}

// round 13
// speedup vs baseline: 1.0320x; 1.0060x over previous
#include <cuda_runtime.h>
#include <cuda_bf16.h>

// Problem constants (fixed by the dataset)
#define MAXN 100000
#define MAXE 3200000
#define INC1 64
#define HIDC 128
#define OUTC2 64
#define CAP 128              // per-node bucket capacity; in-deg ~ Poisson(32), P(>128) ~ 1e-40

// Packed fp32x2 add (sm_100+; ptxas never emits this from C++)
#define ADDF32X2(acc, a) \
    asm("add.rn.f32x2 %0, %0, %1;" : "+l"(acc) : "l"(a))

// ---------------- device scratch (no allocations allowed) ----------------
__device__ float g_buf_o1[MAXN * HIDC];  // relu(layer1 output)            [N,128]
__device__ float g_buf_xs[MAXN * INC1];  // dinv*x, later reused for g2     [N,64]
__device__ float g_buf_a [MAXN * INC1];  // aggregated xs                   [N,64]
__device__ int   g_cursor[MAXN];         // absolute write cursor per bucket
__device__ int   g_col[MAXN * CAP];      // bucketed adjacency (src ids)
__device__ float g_dinv[MAXN];

// ---------------- bucket build ----------------
__global__ void init_cursor_kernel(int n) {
    int i = blockIdx.x * blockDim.x + threadIdx.x;
    if (i < n) g_cursor[i] = i * CAP;
}

// 4 edges per thread via int4 loads; atomic cursor allocates bucket slots.
__global__ void fill_kernel(const int* __restrict__ src,
                            const int* __restrict__ dst, int E) {
    int i = blockIdx.x * blockDim.x + threadIdx.x;
    int e = i << 2;
    if (e + 3 < E) {
        int4 s4 = *reinterpret_cast<const int4*>(src + e);
        int4 d4 = *reinterpret_cast<const int4*>(dst + e);
        g_col[atomicAdd(&g_cursor[d4.x], 1)] = s4.x;
        g_col[atomicAdd(&g_cursor[d4.y], 1)] = s4.y;
        g_col[atomicAdd(&g_cursor[d4.z], 1)] = s4.z;
        g_col[atomicAdd(&g_cursor[d4.w], 1)] = s4.w;
    } else if (e < E) {
        for (int k = e; k < E; k++)
            g_col[atomicAdd(&g_cursor[dst[k]], 1)] = src[k];
    }
}

// ---------------- xs = dinv .* x  (also materializes dinv from cursor) ----------------
__global__ void scale_x_kernel(const float* __restrict__ X, float* __restrict__ XS, int n) {
    int i = blockIdx.x * blockDim.x + threadIdx.x;      // one float4 per thread
    if (i >= n * 16) return;
    int row = i >> 4;
    int cnt = g_cursor[row] - row * CAP;                // in-degree (no self loop)
    float di = rsqrtf((float)(cnt + 1));
    if ((i & 15) == 0) g_dinv[row] = di;
    float4 v = ((const float4*)X)[i];
    v.x *= di; v.y *= di; v.z *= di; v.w *= di;
    ((float4*)XS)[i] = v;
}

// ---------------- Aggregation (bucket gather), one warp per node, 64 ch ----------------
// R12 structure (int4 index fetch + software pipelining) with the accumulator held
// packed: add.rn.f32x2 halves the FADD issue count (8 -> 4 per batch per lane).
// acc init = G[d] (self loop). EPI=1: dinv*acc + b, else raw sum.
template <int EPI>
__global__ void __launch_bounds__(256)
agg64_kernel(const float* __restrict__ G, const float* __restrict__ b,
             float* __restrict__ O, int n) {
    int warp = (blockIdx.x * blockDim.x + threadIdx.x) >> 5;
    int lane = threadIdx.x & 31;
    if (warp >= n) return;
    const int d = warp;
    const unsigned long long* __restrict__ Gv = (const unsigned long long*)G;
    unsigned long long acc = Gv[d * 32 + lane];          // self loop (packed f32x2)
    int e = d * CAP;
    const int end = g_cursor[d];
    int4 s;
    bool have = (e + 4 <= end);
    if (have) s = *reinterpret_cast<const int4*>(g_col + e);
    while (have) {
        int4 c = s;
        e += 4;
        have = (e + 4 <= end);
        if (have) s = *reinterpret_cast<const int4*>(g_col + e);
        unsigned long long a0 = Gv[c.x * 32 + lane];
        unsigned long long a1 = Gv[c.y * 32 + lane];
        unsigned long long a2 = Gv[c.z * 32 + lane];
        unsigned long long a3 = Gv[c.w * 32 + lane];
        ADDF32X2(acc, a0);
        ADDF32X2(acc, a1);
        ADDF32X2(acc, a2);
        ADDF32X2(acc, a3);
    }
    for (; e < end; e++) {
        int si = g_col[e];
        unsigned long long a = Gv[si * 32 + lane];
        ADDF32X2(acc, a);
    }
    float2 r;
    asm("mov.b64 {%0, %1}, %2;" : "=f"(r.x), "=f"(r.y) : "l"(acc));
    if (EPI) {
        const float di = g_dinv[d];
        float2 bi = ((const float2*)b)[lane];
        r.x = di * r.x + bi.x;
        r.y = di * r.y + bi.y;
    }
    ((float2*)O)[d * 32 + lane] = r;
}

// ---------------- GEMM: G[i,:] = epi( X[i,:] @ W ), RR rows per thread ----------------
// EPI=1: relu(dinv*acc + b) ; EPI=0: dinv*acc   (R5/R10-measured configuration)
template <int INC, int OUTC, int TY, int RR, int RPB, int EPI>
__global__ void __launch_bounds__(OUTC * TY)
gemm_kernel(const float* __restrict__ X, const float* __restrict__ W,
            const float* __restrict__ b, float* __restrict__ G, int n) {
    __shared__ float Ws[INC * OUTC];
    __shared__ float Xs[TY * RR][INC];
    const int tx = threadIdx.x;        // output channel
    const int ty = threadIdx.y;
    const int tid = ty * OUTC + tx;
    const int nthr = OUTC * TY;
    for (int i = tid; i < INC * OUTC; i += nthr) Ws[i] = W[i];
    __syncthreads();
    const int ROWS = TY * RR;
    const int base = blockIdx.x * RPB;
    for (int r0 = 0; r0 < RPB; r0 += ROWS) {
        for (int i = tid; i < ROWS * (INC / 4); i += nthr) {
            int rloc = i / (INC / 4);
            int cc = (i % (INC / 4));
            int rr = base + r0 + rloc;
            float4 v = (rr < n) ? ((const float4*)(X + rr * INC))[cc]
                                : make_float4(0.f, 0.f, 0.f, 0.f);
            *(float4*)&Xs[rloc][cc * 4] = v;
        }
        __syncthreads();
        float acc[RR];
#pragma unroll
        for (int r = 0; r < RR; r++) acc[r] = 0.f;
#pragma unroll 8
        for (int k = 0; k < INC; k++) {
            float w = Ws[k * OUTC + tx];
#pragma unroll
            for (int r = 0; r < RR; r++)
                acc[r] += Xs[ty * RR + r][k] * w;
        }
#pragma unroll
        for (int r = 0; r < RR; r++) {
            int row = base + r0 + ty * RR + r;
            if (row < n) {
                float di = g_dinv[row];
                float v = EPI ? fmaxf(di * acc[r] + b[tx], 0.f) : di * acc[r];
                G[row * OUTC + tx] = v;
            }
        }
        __syncthreads();
    }
}

// ---------------- launch ----------------
extern "C" void kernel_launch(void* const* d_in, const int* in_sizes, int n_in,
                              void* d_out, int out_size) {
    const float* x  = (const float*)d_in[0];
    const int*   ei = (const int*)d_in[1];     // int32 (JAX x64-disabled truncates int64)
    const float* W1 = (const float*)d_in[2];
    const float* b1 = (const float*)d_in[3];
    const float* W2 = (const float*)d_in[4];
    const float* b2 = (const float*)d_in[5];
    float* out = (float*)d_out;

    const int n = in_sizes[0] / INC1;     // 100000
    const int E = in_sizes[1] / 2;        // 3200000
    const int* src = ei;
    const int* dst = ei + E;
    const int e4 = (E + 3) / 4;

    float* d_o1 = nullptr; cudaGetSymbolAddress((void**)&d_o1, g_buf_o1);
    float* d_xs = nullptr; cudaGetSymbolAddress((void**)&d_xs, g_buf_xs);
    float* d_a  = nullptr; cudaGetSymbolAddress((void**)&d_a,  g_buf_a);

    // 1) bucketed adjacency build (no count pass, no scan)
    init_cursor_kernel<<<(n + 255) / 256, 256>>>(n);
    fill_kernel<<<(e4 + 255) / 256, 256>>>(src, dst, E);

    // 2) xs = dinv .* x   (also derives dinv from cursors)
    scale_x_kernel<<<(n * 16 + 255) / 256, 256>>>(x, d_xs, n);
    // 3) a[d] = xs[d] + sum_{s in N(d)} xs[s]    (64-ch gather)
    agg64_kernel<0><<<(n * 32 + 255) / 256, 256>>>(d_xs, nullptr, d_a, n);
    // 4) o1 = relu(dinv .* (a @ W1) + b1)        (64 -> 128)
    gemm_kernel<INC1, HIDC, 2, 4, 64, 1><<<(n + 63) / 64, dim3(HIDC, 2)>>>(d_a, W1, b1, d_o1, n);
    // 5) g2 = dinv .* (o1 @ W2)                  (128 -> 64), reuse xs buffer
    gemm_kernel<HIDC, OUTC2, 4, 4, 64, 0><<<(n + 63) / 64, dim3(OUTC2, 4)>>>(d_o1, W2, nullptr, d_xs, n);
    // 6) out[d] = dinv[d] * (g2[d] + sum g2[s]) + b2   (64-ch gather)
    agg64_kernel<1><<<(n * 32 + 255) / 256, 256>>>(d_xs, b2, out, n);
}